// round 8
// baseline (speedup 1.0000x reference)
#include <cuda_runtime.h>
#include <cuda_bf16.h>

// Fixed-shape problem: N=2000 nodes, F=2, HIDDEN=64, K=3, G=256 graphs, E~7998 edges
#define NN    2000
#define EMAXS 8192          // smem edge capacity (actual E ~7998)
#define HID   64
#define TPB   512

typedef unsigned long long ull;

// ---------------- f32x2 packed-math helpers ----------------
__device__ __forceinline__ ull pk2(float lo, float hi) {
    ull r; asm("mov.b64 %0,{%1,%2};" : "=l"(r) : "f"(lo), "f"(hi)); return r;
}
__device__ __forceinline__ void upk2(ull v, float& lo, float& hi) {
    asm("mov.b64 {%0,%1}, %2;" : "=f"(lo), "=f"(hi) : "l"(v));
}
__device__ __forceinline__ ull fma2v(ull a, ull b, ull c) {
    ull d; asm("fma.rn.f32x2 %0, %1, %2, %3;" : "=l"(d) : "l"(a), "l"(b), "l"(c)); return d;
}

// ---------------- device-global scratch ----------------
__device__ int  g_ptr[NN + 1];
__device__ int  g_perm[NN];
__device__ int2 g_edge[EMAXS];   // .x = src slot BYTE OFFSET (slot*16), .y = bits of gcn_norm w

// ---------------- fused prepass: smem atomics + degree counting-sort ----------------
__global__ __launch_bounds__(1024)
void k_pre(const int* __restrict__ row, const int* __restrict__ col,
           const float* __restrict__ ew, int E) {
    __shared__ float sdeg[NN];
    __shared__ int   scnt[NN];
    __shared__ int   sinv[NN];
    __shared__ int   scur[NN];
    __shared__ int   hist[64];
    __shared__ int   hoff[64];
    __shared__ int   warpsum[32];
    const int t = threadIdx.x;

    for (int i = t; i < NN; i += 1024) { sdeg[i] = 0.f; scnt[i] = 0; }
    if (t < 64) hist[t] = 0;
    __syncthreads();

    for (int e = t; e < E; e += 1024) {
        int c = col[e];
        atomicAdd(&sdeg[c], ew[e]);
        atomicAdd(&scnt[c], 1);
    }
    __syncthreads();

    for (int n = t; n < NN; n += 1024) {
        int d = scnt[n]; if (d > 63) d = 63;
        atomicAdd(&hist[d], 1);
    }
    __syncthreads();
    if (t == 0) {
        int run = 0;
        for (int d = 0; d < 64; d++) { hoff[d] = run; run += hist[d]; }
    }
    __syncthreads();

    for (int n = t; n < NN; n += 1024) {
        int d = scnt[n]; int dc = (d > 63) ? 63 : d;
        int slot = atomicAdd(&hoff[dc], 1);
        sinv[n] = slot;
        g_perm[slot] = n;
        scur[slot] = d;
    }
    __syncthreads();

    {   // exclusive scan of slot-degrees -> g_ptr / cursors
        int i0 = 2 * t, i1 = 2 * t + 1;
        int a0 = (i0 < NN) ? scur[i0] : 0;
        int a1 = (i1 < NN) ? scur[i1] : 0;
        int tot = a0 + a1;
        int lane = t & 31, wid = t >> 5;
        int v = tot;
        #pragma unroll
        for (int o = 1; o < 32; o <<= 1) {
            int u = __shfl_up_sync(0xFFFFFFFFu, v, o);
            if (lane >= o) v += u;
        }
        if (lane == 31) warpsum[wid] = v;
        __syncthreads();
        if (wid == 0) {
            int w = warpsum[lane];
            #pragma unroll
            for (int o = 1; o < 32; o <<= 1) {
                int u = __shfl_up_sync(0xFFFFFFFFu, w, o);
                if (lane >= o) w += u;
            }
            warpsum[lane] = w;
        }
        __syncthreads();
        int base = v - tot + (wid ? warpsum[wid - 1] : 0);
        if (i0 < NN) { scur[i0] = base;      g_ptr[i0] = base; }
        if (i1 < NN) { scur[i1] = base + a0; g_ptr[i1] = base + a0; }
        if (t == 0)  g_ptr[NN] = E;
    }
    __syncthreads();

    for (int e = t; e < E; e += 1024) {
        int r = row[e], c = col[e];
        float dr = sdeg[r], dc = sdeg[c];
        float ir = (dr > 0.f) ? rsqrtf(dr) : 0.f;
        float ic = (dc > 0.f) ? rsqrtf(dc) : 0.f;
        float nrm = ir * ew[e] * ic;
        int p = atomicAdd(&scur[sinv[c]], 1);
        g_edge[p] = make_int2(sinv[r] * 16, __float_as_int(nrm));   // BYTE offset
    }
}

// ---------------- main fused kernel: one CTA per TWO graphs ----------------
// Node buffers: ulonglong2 per node = ( pk2(feat0_A, feat0_B), pk2(feat1_A, feat1_B) )
#define SMEM_BYTES (4 * NN * 16 + EMAXS * 8 + 4096 + 4096 + 512 + (NN + 1) * 4)

__global__ __launch_bounds__(TPB, 1)
void k_main(const float* __restrict__ x,
            const float* __restrict__ W1, const float* __restrict__ b1,
            const float* __restrict__ W2, const float* __restrict__ b2,
            float* __restrict__ out, int G, int E) {
    extern __shared__ float sm[];
    ulonglong2* pb0 = (ulonglong2*)sm;
    ulonglong2* pb1 = pb0 + NN;
    ulonglong2* pb2 = pb1 + NN;
    ulonglong2* pb3 = pb2 + NN;
    int2* se  = (int2*)(pb3 + NN);         // staged edges (byte-offset, w bits)
    ull*  w1d = (ull*)(se + EMAXS);        // [64 j][8 i]  pk2(W1cat[i][j], dup)
    ull*  w2d = w1d + 512;                 // [64 j][8 c]  pk2(W2cat[j][c], dup)
    ull*  b1d = w2d + 512;                 // [64] pk2(b1[j], dup)
    int*  sptr = (int*)(b1d + 64);

    const int t  = threadIdx.x;
    const int bs = blockDim.x;
    const int gA = 2 * blockIdx.x;
    int gB = gA + 1; bool hasB = (gB < G); if (!hasB) gB = gA;

    // stage duplicated weights
    for (int i = t; i < 512; i += bs) {
        int j = i >> 3, c = i & 7;
        float a = W1[c * HID + j];                             // W1cat[c][j]
        w1d[i] = pk2(a, a);
        float v = W2[(c >> 1) * (HID * 2) + j * 2 + (c & 1)];  // W2cat[j][c]
        w2d[i] = pk2(v, v);
    }
    for (int i = t; i < HID; i += bs) { float v = b1[i]; b1d[i] = pk2(v, v); }
    for (int i = t; i < NN + 1; i += bs) sptr[i] = g_ptr[i];
    for (int i = t; i < E; i += bs) se[i] = g_edge[i];

    // stage x into slot space with {A,B}-in-lanes transpose -> pb0
    const ull* xgA = (const ull*)(x + (size_t)gA * 2 * NN);
    const ull* xgB = (const ull*)(x + (size_t)gB * 2 * NN);
    for (int s = t; s < NN; s += bs) {
        int node = __ldg(&g_perm[s]);
        float a0, a1, c0, c1;
        upk2(__ldg(&xgA[node]), a0, a1);
        upk2(__ldg(&xgB[node]), c0, c1);
        pb0[s] = make_ulonglong2(pk2(a0, c0), pk2(a1, c1));
    }
    __syncthreads();

    // ---- gather: byte-offset indexed smem loads ----
    #define GATHER(PIN, POUT, ADD, USE_ADD)                                    \
    _Pragma("unroll 1")                                                        \
    for (int n = t; n < NN; n += bs) {                                         \
        int b = sptr[n], e = sptr[n + 1];                                      \
        ull a0 = 0, a1 = 0;                                                    \
        if (USE_ADD) { ulonglong2 z = ADD[n]; a0 = z.x; a1 = z.y; }            \
        const char* pinc = (const char*)PIN;                                   \
        for (int q = b; q < e; q++) {                                          \
            int2 ed = se[q];                                                   \
            float w = __int_as_float(ed.y);                                    \
            ull ww = pk2(w, w);                                                \
            ulonglong2 v = *(const ulonglong2*)(pinc + ed.x);                  \
            a0 = fma2v(v.x, ww, a0); a1 = fma2v(v.y, ww, a1);                  \
        }                                                                      \
        POUT[n] = make_ulonglong2(a0, a1);                                     \
    }

    // layer-1 hops
    GATHER(pb0, pb1, pb0, false); __syncthreads();
    GATHER(pb1, pb2, pb0, false); __syncthreads();
    GATHER(pb2, pb3, pb0, false); __syncthreads();

    // ---- dense sandwich: [8] -> 64 (relu) -> [8]; NPT=2 nodes share weight loads ----
    // 128-reg budget (TPB=512, occ 1): state 64 regs + weights/temps ~ 85-95, no spills.
    {
        const ulonglong2* w1v = (const ulonglong2*)w1d;   // 4 per j
        const ulonglong2* w2v = (const ulonglong2*)w2d;   // 4 per j
        #pragma unroll 1
        for (int sw = 0; sw < 2; sw++) {
            int nA = t + sw * 2 * bs;           // sw0: t       sw1: t+1024   (< NN always)
            int nB = nA + bs;                   // sw0: t+512   sw1: t+1536   (predicated)
            bool vB = (nB < NN);
            int iB = vB ? nB : nA;
            ulonglong2 q0, q1, q2, q3;
            q0 = pb0[nA]; q1 = pb1[nA]; q2 = pb2[nA]; q3 = pb3[nA];
            ull pA0 = q0.x, pA1 = q0.y, pA2 = q1.x, pA3 = q1.y;
            ull pA4 = q2.x, pA5 = q2.y, pA6 = q3.x, pA7 = q3.y;
            q0 = pb0[iB]; q1 = pb1[iB]; q2 = pb2[iB]; q3 = pb3[iB];
            ull pB0 = q0.x, pB1 = q0.y, pB2 = q1.x, pB3 = q1.y;
            ull pB4 = q2.x, pB5 = q2.y, pB6 = q3.x, pB7 = q3.y;
            ull mA0 = 0, mA1 = 0, mA2 = 0, mA3 = 0, mA4 = 0, mA5 = 0, mA6 = 0, mA7 = 0;
            ull mB0 = 0, mB1 = 0, mB2 = 0, mB3 = 0, mB4 = 0, mB5 = 0, mB6 = 0, mB7 = 0;
            #pragma unroll 1
            for (int j = 0; j < HID; j++) {
                ull bb = b1d[j];
                ull hA = bb, hB = bb;
                ulonglong2 w;
                w = w1v[j * 4 + 0];
                hA = fma2v(pA0, w.x, hA); hA = fma2v(pA1, w.y, hA);
                hB = fma2v(pB0, w.x, hB); hB = fma2v(pB1, w.y, hB);
                w = w1v[j * 4 + 1];
                hA = fma2v(pA2, w.x, hA); hA = fma2v(pA3, w.y, hA);
                hB = fma2v(pB2, w.x, hB); hB = fma2v(pB3, w.y, hB);
                w = w1v[j * 4 + 2];
                hA = fma2v(pA4, w.x, hA); hA = fma2v(pA5, w.y, hA);
                hB = fma2v(pB4, w.x, hB); hB = fma2v(pB5, w.y, hB);
                w = w1v[j * 4 + 3];
                hA = fma2v(pA6, w.x, hA); hA = fma2v(pA7, w.y, hA);
                hB = fma2v(pB6, w.x, hB); hB = fma2v(pB7, w.y, hB);
                float u0, u1;
                upk2(hA, u0, u1); u0 = fmaxf(u0, 0.f); u1 = fmaxf(u1, 0.f); hA = pk2(u0, u1);
                upk2(hB, u0, u1); u0 = fmaxf(u0, 0.f); u1 = fmaxf(u1, 0.f); hB = pk2(u0, u1);
                w = w2v[j * 4 + 0];
                mA0 = fma2v(hA, w.x, mA0); mA1 = fma2v(hA, w.y, mA1);
                mB0 = fma2v(hB, w.x, mB0); mB1 = fma2v(hB, w.y, mB1);
                w = w2v[j * 4 + 1];
                mA2 = fma2v(hA, w.x, mA2); mA3 = fma2v(hA, w.y, mA3);
                mB2 = fma2v(hB, w.x, mB2); mB3 = fma2v(hB, w.y, mB3);
                w = w2v[j * 4 + 2];
                mA4 = fma2v(hA, w.x, mA4); mA5 = fma2v(hA, w.y, mA5);
                mB4 = fma2v(hB, w.x, mB4); mB5 = fma2v(hB, w.y, mB5);
                w = w2v[j * 4 + 3];
                mA6 = fma2v(hA, w.x, mA6); mA7 = fma2v(hA, w.y, mA7);
                mB6 = fma2v(hB, w.x, mB6); mB7 = fma2v(hB, w.y, mB7);
            }
            pb0[nA] = make_ulonglong2(mA0, mA1);
            pb1[nA] = make_ulonglong2(mA2, mA3);
            pb2[nA] = make_ulonglong2(mA4, mA5);
            pb3[nA] = make_ulonglong2(mA6, mA7);
            if (vB) {
                pb0[nB] = make_ulonglong2(mB0, mB1);
                pb1[nB] = make_ulonglong2(mB2, mB3);
                pb2[nB] = make_ulonglong2(mB4, mB5);
                pb3[nB] = make_ulonglong2(mB6, mB7);
            }
        }
    }
    __syncthreads();

    // layer-2 Horner (in-place addends safe: each ADD[n] owned by its thread):
    GATHER(pb3, pb2, pb2, true); __syncthreads();   // pb2 <- m2 + A m3
    GATHER(pb2, pb1, pb1, true); __syncthreads();   // pb1 <- m1 + A pb2

    // epilogue: out = x + m0 + A pb1 + b2 (x reloaded from gmem via perm)
    float b20 = b2[0], b21 = b2[1];
    float2* ogA = (float2*)out + (size_t)gA * NN;
    float2* ogB = (float2*)out + (size_t)gB * NN;
    #pragma unroll 1
    for (int n = t; n < NN; n += bs) {
        int b = sptr[n], e = sptr[n + 1];
        ulonglong2 z = pb0[n];
        ull a0 = z.x, a1 = z.y;
        const char* pinc = (const char*)pb1;
        for (int q = b; q < e; q++) {
            int2 ed = se[q];
            float w = __int_as_float(ed.y);
            ull ww = pk2(w, w);
            ulonglong2 v = *(const ulonglong2*)(pinc + ed.x);
            a0 = fma2v(v.x, ww, a0); a1 = fma2v(v.y, ww, a1);
        }
        int node = __ldg(&g_perm[n]);
        float oA0, oB0, oA1, oB1;
        upk2(a0, oA0, oB0); upk2(a1, oA1, oB1);
        float xA0, xA1, xB0, xB1;
        upk2(__ldg(&xgA[node]), xA0, xA1);
        ogA[node] = make_float2(xA0 + oA0 + b20, xA1 + oA1 + b21);
        if (hasB) {
            upk2(__ldg(&xgB[node]), xB0, xB1);
            ogB[node] = make_float2(xB0 + oB0 + b20, xB1 + oB1 + b21);
        }
    }
    #undef GATHER
}

// ---------------- launcher ----------------
extern "C" void kernel_launch(void* const* d_in, const int* in_sizes, int n_in,
                              void* d_out, int out_size) {
    const float* x   = (const float*)d_in[0];
    const int*   row = (const int*)  d_in[1];
    const int*   col = (const int*)  d_in[2];
    const float* ew  = (const float*)d_in[3];
    const float* W1  = (const float*)d_in[4];
    const float* b1  = (const float*)d_in[5];
    const float* W2  = (const float*)d_in[6];
    const float* b2  = (const float*)d_in[7];

    const int E = in_sizes[1];
    const int G = in_sizes[0] / (2 * NN);
    const int nCta = (G + 1) / 2;

    cudaFuncSetAttribute(k_main, cudaFuncAttributeMaxDynamicSharedMemorySize, SMEM_BYTES);

    k_pre<<<1, 1024>>>(row, col, ew, E);
    k_main<<<nCta, TPB, SMEM_BYTES>>>(x, W1, b1, W2, b2, (float*)d_out, G, E);
}

// round 9
// speedup vs baseline: 1.5160x; 1.5160x over previous
#include <cuda_runtime.h>
#include <cuda_bf16.h>

// Fixed-shape problem: N=2000 nodes, F=2, HIDDEN=64, K=3, G=256 graphs, E~7998 edges
#define NN    2000
#define EMAX  20000
#define HID   64
#define TPB   1024

typedef unsigned long long ull;

// ---------------- f32x2 packed-math helpers (sm_100+ PTX) ----------------
__device__ __forceinline__ ull pk2(float lo, float hi) {
    ull r; asm("mov.b64 %0,{%1,%2};" : "=l"(r) : "f"(lo), "f"(hi)); return r;
}
__device__ __forceinline__ void upk2(ull v, float& lo, float& hi) {
    asm("mov.b64 {%0,%1}, %2;" : "=f"(lo), "=f"(hi) : "l"(v));
}
__device__ __forceinline__ ull fma2v(ull a, ull b, ull c) {
    ull d; asm("fma.rn.f32x2 %0, %1, %2, %3;" : "=l"(d) : "l"(a), "l"(b), "l"(c)); return d;
}

// ---------------- device-global scratch ----------------
__device__ int  g_ptr[NN + 1];    // CSR row pointers (slot space, by destination)
__device__ int  g_perm[NN];       // perm[slot] = original node id
__device__ int2 g_edge[EMAX];     // .x = src slot BYTE offset (slot*16), .y = gcn_norm bits

// ---------------- fused prepass: smem atomics + degree counting-sort ----------------
__global__ __launch_bounds__(1024)
void k_pre(const int* __restrict__ row, const int* __restrict__ col,
           const float* __restrict__ ew, int E) {
    __shared__ float sdeg[NN];
    __shared__ int   scnt[NN];
    __shared__ int   sinv[NN];
    __shared__ int   scur[NN];
    __shared__ int   hist[64];
    __shared__ int   hoff[64];
    __shared__ int   warpsum[32];
    const int t = threadIdx.x;

    for (int i = t; i < NN; i += 1024) { sdeg[i] = 0.f; scnt[i] = 0; }
    if (t < 64) hist[t] = 0;
    __syncthreads();

    for (int e = t; e < E; e += 1024) {
        int c = col[e];
        atomicAdd(&sdeg[c], ew[e]);
        atomicAdd(&scnt[c], 1);
    }
    __syncthreads();

    for (int n = t; n < NN; n += 1024) {
        int d = scnt[n]; if (d > 63) d = 63;
        atomicAdd(&hist[d], 1);
    }
    __syncthreads();
    if (t == 0) {
        int run = 0;
        for (int d = 0; d < 64; d++) { hoff[d] = run; run += hist[d]; }
    }
    __syncthreads();

    for (int n = t; n < NN; n += 1024) {
        int d = scnt[n]; int dc = (d > 63) ? 63 : d;
        int slot = atomicAdd(&hoff[dc], 1);
        sinv[n] = slot;
        g_perm[slot] = n;
        scur[slot] = d;
    }
    __syncthreads();

    {   // exclusive scan of slot-degrees -> g_ptr / cursors
        int i0 = 2 * t, i1 = 2 * t + 1;
        int a0 = (i0 < NN) ? scur[i0] : 0;
        int a1 = (i1 < NN) ? scur[i1] : 0;
        int tot = a0 + a1;
        int lane = t & 31, wid = t >> 5;
        int v = tot;
        #pragma unroll
        for (int o = 1; o < 32; o <<= 1) {
            int u = __shfl_up_sync(0xFFFFFFFFu, v, o);
            if (lane >= o) v += u;
        }
        if (lane == 31) warpsum[wid] = v;
        __syncthreads();
        if (wid == 0) {
            int w = warpsum[lane];
            #pragma unroll
            for (int o = 1; o < 32; o <<= 1) {
                int u = __shfl_up_sync(0xFFFFFFFFu, w, o);
                if (lane >= o) w += u;
            }
            warpsum[lane] = w;
        }
        __syncthreads();
        int base = v - tot + (wid ? warpsum[wid - 1] : 0);
        if (i0 < NN) { scur[i0] = base;      g_ptr[i0] = base; }
        if (i1 < NN) { scur[i1] = base + a0; g_ptr[i1] = base + a0; }
        if (t == 0)  g_ptr[NN] = E;
    }
    __syncthreads();

    for (int e = t; e < E; e += 1024) {
        int r = row[e], c = col[e];
        float dr = sdeg[r], dc = sdeg[c];
        float ir = (dr > 0.f) ? rsqrtf(dr) : 0.f;
        float ic = (dc > 0.f) ? rsqrtf(dc) : 0.f;
        float nrm = ir * ew[e] * ic;
        int p = atomicAdd(&scur[sinv[c]], 1);
        g_edge[p] = make_int2(sinv[r] * 16, __float_as_int(nrm));   // BYTE offset
    }
}

// ---------------- main fused kernel: one CTA per TWO graphs (R4 structure) ----------------
// buffers hold {graphA pair, graphB pair} per node as ulonglong2 (16 B)
#define SMEM_BYTES (6 * NN * 16 + 2048 + 2048 + 256 + (NN + 1) * 4)

// gather with depth-2 edge prefetch: pout[n] = (addbuf? addbuf[n]:0) + A * pin
__device__ __forceinline__ void gather_hop2(const ulonglong2* __restrict__ pin,
                                            ulonglong2* __restrict__ pout,
                                            const ulonglong2* __restrict__ addbuf,
                                            const int* __restrict__ sptr,
                                            int t, int bs) {
    const char* pinc = (const char*)pin;
    #pragma unroll 1
    for (int n = t; n < NN; n += bs) {
        int b = sptr[n], e = sptr[n + 1];
        ull accA = 0ull, accB = 0ull;
        if (addbuf) { ulonglong2 a = addbuf[n]; accA = a.x; accB = a.y; }
        int2 e0, e1;
        if (b < e)     e0 = __ldg(&g_edge[b]);
        if (b + 1 < e) e1 = __ldg(&g_edge[b + 1]);
        #pragma unroll 1
        for (int q = b; q < e; q++) {
            int2 cur = e0;
            e0 = e1;
            if (q + 2 < e) e1 = __ldg(&g_edge[q + 2]);
            float w = __int_as_float(cur.y);
            ull ww = pk2(w, w);
            ulonglong2 v = *(const ulonglong2*)(pinc + cur.x);
            accA = fma2v(v.x, ww, accA);
            accB = fma2v(v.y, ww, accB);
        }
        pout[n] = make_ulonglong2(accA, accB);
    }
}

__global__ __launch_bounds__(TPB, 1)
void k_main(const float* __restrict__ x,
            const float* __restrict__ W1, const float* __restrict__ b1,
            const float* __restrict__ W2, const float* __restrict__ b2,
            float* __restrict__ out, int G) {
    extern __shared__ float sm[];
    ulonglong2* pb0     = (ulonglong2*)sm;
    ulonglong2* pb1     = pb0 + NN;
    ulonglong2* pb2     = pb1 + NN;
    ulonglong2* pb3     = pb2 + NN;
    ulonglong2* scratch = pb3 + NN;
    ulonglong2* xbuf    = scratch + NN;
    float* w1q = (float*)(xbuf + NN);    // [32 jp][8 i][2 half]
    float* w2q = w1q + 512;              // [32 jp][2 jj][8 c]
    float* b1s = w2q + 512;
    int*   sptr = (int*)(b1s + 64);

    const int t  = threadIdx.x;
    const int bs = blockDim.x;
    const int gA = 2 * blockIdx.x;
    int gB = gA + 1; bool hasB = (gB < G); if (!hasB) gB = gA;

    // stage packed weights
    for (int i = t; i < 512; i += bs) {
        int jp = i >> 4, rem = i & 15;
        {   int ii = rem >> 1, half = rem & 1;
            w1q[i] = W1[ii * HID + 2 * jp + half]; }
        {   int jj = rem >> 3, c = rem & 7;
            int j = 2 * jp + jj;
            w2q[i] = W2[(c >> 1) * (HID * 2) + j * 2 + (c & 1)]; }
    }
    for (int i = t; i < HID; i += bs) b1s[i] = b1[i];
    for (int i = t; i < NN + 1; i += bs) sptr[i] = g_ptr[i];

    // stage x into slot space (permuted gather, both graphs)
    const ull* xgA = (const ull*)(x + (size_t)gA * 2 * NN);
    const ull* xgB = (const ull*)(x + (size_t)gB * 2 * NN);
    for (int s = t; s < NN; s += bs) {
        int node = __ldg(&g_perm[s]);
        ulonglong2 v = make_ulonglong2(__ldg(&xgA[node]), __ldg(&xgB[node]));
        xbuf[s] = v; pb0[s] = v;
    }
    __syncthreads();

    // layer-1 hops
    gather_hop2(pb0, pb1, nullptr, sptr, t, bs); __syncthreads();
    gather_hop2(pb1, pb2, nullptr, sptr, t, bs); __syncthreads();
    gather_hop2(pb2, pb3, nullptr, sptr, t, bs); __syncthreads();

    // dense per-node sandwich: [8] -> 64 (relu) -> [8]; both graphs share weight + p loads
    {
        const ulonglong2* w1v = (const ulonglong2*)w1q;
        const ulonglong2* w2v = (const ulonglong2*)w2q;
        const ull* b1v = (const ull*)b1s;
        for (int n = t; n < NN; n += bs) {
            ulonglong2 a0 = pb0[n], a1 = pb1[n], a2 = pb2[n], a3 = pb3[n];
            float f0, f1;
            upk2(a0.x, f0, f1); ull pA0 = pk2(f0, f0), pA1 = pk2(f1, f1);
            upk2(a1.x, f0, f1); ull pA2 = pk2(f0, f0), pA3 = pk2(f1, f1);
            upk2(a2.x, f0, f1); ull pA4 = pk2(f0, f0), pA5 = pk2(f1, f1);
            upk2(a3.x, f0, f1); ull pA6 = pk2(f0, f0), pA7 = pk2(f1, f1);
            upk2(a0.y, f0, f1); ull pB0 = pk2(f0, f0), pB1 = pk2(f1, f1);
            upk2(a1.y, f0, f1); ull pB2 = pk2(f0, f0), pB3 = pk2(f1, f1);
            upk2(a2.y, f0, f1); ull pB4 = pk2(f0, f0), pB5 = pk2(f1, f1);
            upk2(a3.y, f0, f1); ull pB6 = pk2(f0, f0), pB7 = pk2(f1, f1);
            ull mA0 = 0, mA1 = 0, mA2 = 0, mA3 = 0;
            ull mB0 = 0, mB1 = 0, mB2 = 0, mB3 = 0;
            #pragma unroll 4
            for (int jp = 0; jp < 32; jp++) {
                ulonglong2 qa = w1v[jp * 4 + 0], qb = w1v[jp * 4 + 1];
                ulonglong2 qc = w1v[jp * 4 + 2], qd = w1v[jp * 4 + 3];
                ull bb = b1v[jp];
                ull hA = bb, hB = bb;
                hA = fma2v(pA0, qa.x, hA); hA = fma2v(pA1, qa.y, hA);
                hA = fma2v(pA2, qb.x, hA); hA = fma2v(pA3, qb.y, hA);
                hA = fma2v(pA4, qc.x, hA); hA = fma2v(pA5, qc.y, hA);
                hA = fma2v(pA6, qd.x, hA); hA = fma2v(pA7, qd.y, hA);
                hB = fma2v(pB0, qa.x, hB); hB = fma2v(pB1, qa.y, hB);
                hB = fma2v(pB2, qb.x, hB); hB = fma2v(pB3, qb.y, hB);
                hB = fma2v(pB4, qc.x, hB); hB = fma2v(pB5, qc.y, hB);
                hB = fma2v(pB6, qd.x, hB); hB = fma2v(pB7, qd.y, hB);
                float hA0, hA1, hB0, hB1;
                upk2(hA, hA0, hA1); upk2(hB, hB0, hB1);
                hA0 = fmaxf(hA0, 0.f); hA1 = fmaxf(hA1, 0.f);
                hB0 = fmaxf(hB0, 0.f); hB1 = fmaxf(hB1, 0.f);
                ull hA0p = pk2(hA0, hA0), hA1p = pk2(hA1, hA1);
                ull hB0p = pk2(hB0, hB0), hB1p = pk2(hB1, hB1);
                ulonglong2 ra = w2v[jp * 4 + 0], rb = w2v[jp * 4 + 1];
                ulonglong2 rc = w2v[jp * 4 + 2], rd = w2v[jp * 4 + 3];
                mA0 = fma2v(hA0p, ra.x, mA0); mA1 = fma2v(hA0p, ra.y, mA1);
                mA2 = fma2v(hA0p, rb.x, mA2); mA3 = fma2v(hA0p, rb.y, mA3);
                mA0 = fma2v(hA1p, rc.x, mA0); mA1 = fma2v(hA1p, rc.y, mA1);
                mA2 = fma2v(hA1p, rd.x, mA2); mA3 = fma2v(hA1p, rd.y, mA3);
                mB0 = fma2v(hB0p, ra.x, mB0); mB1 = fma2v(hB0p, ra.y, mB1);
                mB2 = fma2v(hB0p, rb.x, mB2); mB3 = fma2v(hB0p, rb.y, mB3);
                mB0 = fma2v(hB1p, rc.x, mB0); mB1 = fma2v(hB1p, rc.y, mB1);
                mB2 = fma2v(hB1p, rd.x, mB2); mB3 = fma2v(hB1p, rd.y, mB3);
            }
            pb0[n] = make_ulonglong2(mA0, mB0);
            pb1[n] = make_ulonglong2(mA1, mB1);
            pb2[n] = make_ulonglong2(mA2, mB2);
            pb3[n] = make_ulonglong2(mA3, mB3);
        }
    }
    __syncthreads();

    // layer-2 Horner: out2 = m0 + A(m1 + A(m2 + A m3))
    gather_hop2(pb3, scratch, pb2, sptr, t, bs); __syncthreads();
    gather_hop2(scratch, pb3, pb1, sptr, t, bs); __syncthreads();

    // final: out = x + m0 + A pb3 + b2 (scatter back through perm, both graphs)
    float b20 = b2[0], b21 = b2[1];
    float2* ogA = (float2*)out + (size_t)gA * NN;
    float2* ogB = (float2*)out + (size_t)gB * NN;
    const char* pinc = (const char*)pb3;
    #pragma unroll 1
    for (int s = t; s < NN; s += bs) {
        int b = sptr[s], e = sptr[s + 1];
        ulonglong2 m0 = pb0[s];
        ull accA = m0.x, accB = m0.y;
        int2 e0, e1;
        if (b < e)     e0 = __ldg(&g_edge[b]);
        if (b + 1 < e) e1 = __ldg(&g_edge[b + 1]);
        #pragma unroll 1
        for (int q = b; q < e; q++) {
            int2 cur = e0;
            e0 = e1;
            if (q + 2 < e) e1 = __ldg(&g_edge[q + 2]);
            float w = __int_as_float(cur.y);
            ull ww = pk2(w, w);
            ulonglong2 v = *(const ulonglong2*)(pinc + cur.x);
            accA = fma2v(v.x, ww, accA);
            accB = fma2v(v.y, ww, accB);
        }
        ulonglong2 xv = xbuf[s];
        int node = __ldg(&g_perm[s]);
        float ox, oy, xl, xh;
        upk2(accA, ox, oy); upk2(xv.x, xl, xh);
        ogA[node] = make_float2(xl + ox + b20, xh + oy + b21);
        if (hasB) {
            upk2(accB, ox, oy); upk2(xv.y, xl, xh);
            ogB[node] = make_float2(xl + ox + b20, xh + oy + b21);
        }
    }
}

// ---------------- launcher ----------------
extern "C" void kernel_launch(void* const* d_in, const int* in_sizes, int n_in,
                              void* d_out, int out_size) {
    const float* x   = (const float*)d_in[0];
    const int*   row = (const int*)  d_in[1];
    const int*   col = (const int*)  d_in[2];
    const float* ew  = (const float*)d_in[3];
    const float* W1  = (const float*)d_in[4];
    const float* b1  = (const float*)d_in[5];
    const float* W2  = (const float*)d_in[6];
    const float* b2  = (const float*)d_in[7];

    const int E = in_sizes[1];
    const int G = in_sizes[0] / (2 * NN);
    const int nCta = (G + 1) / 2;

    cudaFuncSetAttribute(k_main, cudaFuncAttributeMaxDynamicSharedMemorySize, SMEM_BYTES);

    k_pre<<<1, 1024>>>(row, col, ew, E);
    k_main<<<nCta, TPB, SMEM_BYTES>>>(x, W1, b1, W2, b2, (float*)d_out, G);
}

// round 10
// speedup vs baseline: 1.7470x; 1.1524x over previous
#include <cuda_runtime.h>
#include <cuda_bf16.h>

// Fixed-shape problem: N=2000 nodes, F=2, HIDDEN=64, K=3, G=256 graphs, E~7998 edges
#define NN    2000
#define EMAXS 8192          // smem edge capacity (actual E ~7998)
#define HID   64
#define TPB   1024

typedef unsigned long long ull;

// ---------------- f32x2 packed-math helpers (sm_100+ PTX) ----------------
__device__ __forceinline__ ull pk2(float lo, float hi) {
    ull r; asm("mov.b64 %0,{%1,%2};" : "=l"(r) : "f"(lo), "f"(hi)); return r;
}
__device__ __forceinline__ void upk2(ull v, float& lo, float& hi) {
    asm("mov.b64 {%0,%1}, %2;" : "=f"(lo), "=f"(hi) : "l"(v));
}
__device__ __forceinline__ ull fma2v(ull a, ull b, ull c) {
    ull d; asm("fma.rn.f32x2 %0, %1, %2, %3;" : "=l"(d) : "l"(a), "l"(b), "l"(c)); return d;
}

// ---------------- single fused kernel: one CTA per TWO graphs ----------------
// smem: pb0..pb3 (ulonglong2[NN] each) | sedge int2[EMAXS] | w1q/w2q/b1s | sperm | sptr
// Node buffers: ulonglong2 per node = { graphA pair(f0,f1), graphB pair(f0,f1) }
#define SMEM_BYTES (4 * NN * 16 + EMAXS * 8 + 2048 + 2048 + 256 + NN * 4 + (NN + 1) * 4)

__global__ __launch_bounds__(TPB, 1)
void k_main(const float* __restrict__ x,
            const int* __restrict__ row, const int* __restrict__ col,
            const float* __restrict__ ew,
            const float* __restrict__ W1, const float* __restrict__ b1,
            const float* __restrict__ W2, const float* __restrict__ b2,
            float* __restrict__ out, int G, int E) {
    extern __shared__ float sm[];
    ulonglong2* pb0 = (ulonglong2*)sm;
    ulonglong2* pb1 = pb0 + NN;
    ulonglong2* pb2 = pb1 + NN;
    ulonglong2* pb3 = pb2 + NN;
    int2*  sedge = (int2*)(pb3 + NN);       // CSR edges: (src slot byte-offset, w bits)
    float* w1q = (float*)(sedge + EMAXS);   // [32 jp][8 i][2 half]
    float* w2q = w1q + 512;                 // [32 jp][2 jj][8 c]
    float* b1s = w2q + 512;
    int*   sperm = (int*)(b1s + 64);        // slot -> node
    int*   sptr  = sperm + NN;              // CSR row pointers [NN+1]

    // ---- prepass overlays (dead once staging begins) ----
    float* sdeg = (float*)pb0;              // [NN]
    int*   scnt = (int*)pb0 + 2048;         // [NN]
    int*   sinv = (int*)pb1;                // [NN] node -> slot
    int*   scur = (int*)pb1 + 2048;         // [NN] slot degree / cursor
    int*   hist = (int*)pb2;                // [64]
    int*   hoff = hist + 64;                // [64]
    int*   wsum = hoff + 64;                // [32]

    const int t  = threadIdx.x;
    const int bs = blockDim.x;
    if (E > EMAXS) return;   // shape guard (never taken for this problem)

    // ================= in-CTA prepass (identical in every CTA) =================
    for (int i = t; i < NN; i += bs) { sdeg[i] = 0.f; scnt[i] = 0; }
    if (t < 64) hist[t] = 0;
    __syncthreads();

    for (int e = t; e < E; e += bs) {
        int c = col[e];
        atomicAdd(&sdeg[c], ew[e]);
        atomicAdd(&scnt[c], 1);
    }
    __syncthreads();

    for (int n = t; n < NN; n += bs) {
        int d = scnt[n]; if (d > 63) d = 63;
        atomicAdd(&hist[d], 1);
    }
    __syncthreads();
    if (t == 0) {
        int run = 0;
        for (int d = 0; d < 64; d++) { hoff[d] = run; run += hist[d]; }
    }
    __syncthreads();

    for (int n = t; n < NN; n += bs) {
        int d = scnt[n]; int dc = (d > 63) ? 63 : d;
        int slot = atomicAdd(&hoff[dc], 1);
        sinv[n] = slot;
        sperm[slot] = n;
        scur[slot] = d;
    }
    __syncthreads();

    {   // exclusive scan of slot-degrees -> sptr, scur as cursors
        int i0 = 2 * t, i1 = 2 * t + 1;
        int a0 = (i0 < NN) ? scur[i0] : 0;
        int a1 = (i1 < NN) ? scur[i1] : 0;
        int tot = a0 + a1;
        int lane = t & 31, wid = t >> 5;
        int v = tot;
        #pragma unroll
        for (int o = 1; o < 32; o <<= 1) {
            int u = __shfl_up_sync(0xFFFFFFFFu, v, o);
            if (lane >= o) v += u;
        }
        if (lane == 31) wsum[wid] = v;
        __syncthreads();
        if (wid == 0) {
            int w = wsum[lane];
            #pragma unroll
            for (int o = 1; o < 32; o <<= 1) {
                int u = __shfl_up_sync(0xFFFFFFFFu, w, o);
                if (lane >= o) w += u;
            }
            wsum[lane] = w;
        }
        __syncthreads();
        int base = v - tot + (wid ? wsum[wid - 1] : 0);
        if (i0 < NN) sptr[i0] = base;
        if (i1 < NN) sptr[i1] = base + a0;
        if (t == 0)  sptr[NN] = E;
        __syncthreads();
        if (i0 < NN) scur[i0] = sptr[i0];
        if (i1 < NN) scur[i1] = sptr[i1];
    }
    __syncthreads();

    for (int e = t; e < E; e += bs) {
        int r = row[e], c = col[e];
        float dr = sdeg[r], dc = sdeg[c];
        float ir = (dr > 0.f) ? rsqrtf(dr) : 0.f;
        float ic = (dc > 0.f) ? rsqrtf(dc) : 0.f;
        float nrm = ir * ew[e] * ic;
        int p = atomicAdd(&scur[sinv[c]], 1);
        sedge[p] = make_int2(sinv[r] * 16, __float_as_int(nrm));   // BYTE offset
    }
    __syncthreads();
    // ================= prepass done; overlays now dead =================

    const int gA = 2 * blockIdx.x;
    int gB = gA + 1; bool hasB = (gB < G); if (!hasB) gB = gA;

    // stage packed weights
    for (int i = t; i < 512; i += bs) {
        int jp = i >> 4, rem = i & 15;
        {   int ii = rem >> 1, half = rem & 1;
            w1q[i] = W1[ii * HID + 2 * jp + half]; }
        {   int jj = rem >> 3, c = rem & 7;
            int j = 2 * jp + jj;
            w2q[i] = W2[(c >> 1) * (HID * 2) + j * 2 + (c & 1)]; }
    }
    for (int i = t; i < HID; i += bs) b1s[i] = b1[i];

    // stage x into slot space (permuted gather, both graphs) -> pb0
    const ull* xgA = (const ull*)(x + (size_t)gA * 2 * NN);
    const ull* xgB = (const ull*)(x + (size_t)gB * 2 * NN);
    for (int s = t; s < NN; s += bs) {
        int node = sperm[s];
        pb0[s] = make_ulonglong2(__ldg(&xgA[node]), __ldg(&xgB[node]));
    }
    __syncthreads();

    // ---- gather from smem edges: pout[n] = (USE_ADD? ADD[n]:0) + A * pin ----
    #define GATHER(PIN, POUT, ADD, USE_ADD)                                    \
    {   const char* pinc = (const char*)(PIN);                                 \
        _Pragma("unroll 1")                                                    \
        for (int n = t; n < NN; n += bs) {                                     \
            int b = sptr[n], e = sptr[n + 1];                                  \
            ull a0 = 0ull, a1 = 0ull;                                          \
            if (USE_ADD) { ulonglong2 z = (ADD)[n]; a0 = z.x; a1 = z.y; }      \
            _Pragma("unroll 1")                                                \
            for (int q = b; q < e; q++) {                                      \
                int2 ed = sedge[q];                                            \
                float w = __int_as_float(ed.y);                                \
                ull ww = pk2(w, w);                                            \
                ulonglong2 v = *(const ulonglong2*)(pinc + ed.x);              \
                a0 = fma2v(v.x, ww, a0);                                       \
                a1 = fma2v(v.y, ww, a1);                                       \
            }                                                                  \
            (POUT)[n] = make_ulonglong2(a0, a1);                               \
        }                                                                      \
    }

    // layer-1 hops
    GATHER(pb0, pb1, pb0, false); __syncthreads();
    GATHER(pb1, pb2, pb0, false); __syncthreads();
    GATHER(pb2, pb3, pb0, false); __syncthreads();

    // ---- dense per-node sandwich (verbatim R9): [8] -> 64 (relu) -> [8] ----
    {
        const ulonglong2* w1v = (const ulonglong2*)w1q;
        const ulonglong2* w2v = (const ulonglong2*)w2q;
        const ull* b1v = (const ull*)b1s;
        for (int n = t; n < NN; n += bs) {
            ulonglong2 a0 = pb0[n], a1 = pb1[n], a2 = pb2[n], a3 = pb3[n];
            float f0, f1;
            upk2(a0.x, f0, f1); ull pA0 = pk2(f0, f0), pA1 = pk2(f1, f1);
            upk2(a1.x, f0, f1); ull pA2 = pk2(f0, f0), pA3 = pk2(f1, f1);
            upk2(a2.x, f0, f1); ull pA4 = pk2(f0, f0), pA5 = pk2(f1, f1);
            upk2(a3.x, f0, f1); ull pA6 = pk2(f0, f0), pA7 = pk2(f1, f1);
            upk2(a0.y, f0, f1); ull pB0 = pk2(f0, f0), pB1 = pk2(f1, f1);
            upk2(a1.y, f0, f1); ull pB2 = pk2(f0, f0), pB3 = pk2(f1, f1);
            upk2(a2.y, f0, f1); ull pB4 = pk2(f0, f0), pB5 = pk2(f1, f1);
            upk2(a3.y, f0, f1); ull pB6 = pk2(f0, f0), pB7 = pk2(f1, f1);
            ull mA0 = 0, mA1 = 0, mA2 = 0, mA3 = 0;
            ull mB0 = 0, mB1 = 0, mB2 = 0, mB3 = 0;
            #pragma unroll 4
            for (int jp = 0; jp < 32; jp++) {
                ulonglong2 qa = w1v[jp * 4 + 0], qb = w1v[jp * 4 + 1];
                ulonglong2 qc = w1v[jp * 4 + 2], qd = w1v[jp * 4 + 3];
                ull bb = b1v[jp];
                ull hA = bb, hB = bb;
                hA = fma2v(pA0, qa.x, hA); hA = fma2v(pA1, qa.y, hA);
                hA = fma2v(pA2, qb.x, hA); hA = fma2v(pA3, qb.y, hA);
                hA = fma2v(pA4, qc.x, hA); hA = fma2v(pA5, qc.y, hA);
                hA = fma2v(pA6, qd.x, hA); hA = fma2v(pA7, qd.y, hA);
                hB = fma2v(pB0, qa.x, hB); hB = fma2v(pB1, qa.y, hB);
                hB = fma2v(pB2, qb.x, hB); hB = fma2v(pB3, qb.y, hB);
                hB = fma2v(pB4, qc.x, hB); hB = fma2v(pB5, qc.y, hB);
                hB = fma2v(pB6, qd.x, hB); hB = fma2v(pB7, qd.y, hB);
                float hA0, hA1, hB0, hB1;
                upk2(hA, hA0, hA1); upk2(hB, hB0, hB1);
                hA0 = fmaxf(hA0, 0.f); hA1 = fmaxf(hA1, 0.f);
                hB0 = fmaxf(hB0, 0.f); hB1 = fmaxf(hB1, 0.f);
                ull hA0p = pk2(hA0, hA0), hA1p = pk2(hA1, hA1);
                ull hB0p = pk2(hB0, hB0), hB1p = pk2(hB1, hB1);
                ulonglong2 ra = w2v[jp * 4 + 0], rb = w2v[jp * 4 + 1];
                ulonglong2 rc = w2v[jp * 4 + 2], rd = w2v[jp * 4 + 3];
                mA0 = fma2v(hA0p, ra.x, mA0); mA1 = fma2v(hA0p, ra.y, mA1);
                mA2 = fma2v(hA0p, rb.x, mA2); mA3 = fma2v(hA0p, rb.y, mA3);
                mA0 = fma2v(hA1p, rc.x, mA0); mA1 = fma2v(hA1p, rc.y, mA1);
                mA2 = fma2v(hA1p, rd.x, mA2); mA3 = fma2v(hA1p, rd.y, mA3);
                mB0 = fma2v(hB0p, ra.x, mB0); mB1 = fma2v(hB0p, ra.y, mB1);
                mB2 = fma2v(hB0p, rb.x, mB2); mB3 = fma2v(hB0p, rb.y, mB3);
                mB0 = fma2v(hB1p, rc.x, mB0); mB1 = fma2v(hB1p, rc.y, mB1);
                mB2 = fma2v(hB1p, rd.x, mB2); mB3 = fma2v(hB1p, rd.y, mB3);
            }
            pb0[n] = make_ulonglong2(mA0, mB0);   // m0
            pb1[n] = make_ulonglong2(mA1, mB1);   // m1
            pb2[n] = make_ulonglong2(mA2, mB2);   // m2
            pb3[n] = make_ulonglong2(mA3, mB3);   // m3
        }
    }
    __syncthreads();

    // layer-2 Horner, in-place addends (ADD[n] read only by its owning thread):
    GATHER(pb3, pb2, pb2, true); __syncthreads();   // pb2 <- m2 + A m3
    GATHER(pb2, pb1, pb1, true); __syncthreads();   // pb1 <- m1 + A pb2

    // epilogue: out = x + m0 + A pb1 + b2 (x reloaded from gmem via perm)
    {
        float b20 = b2[0], b21 = b2[1];
        float2* ogA = (float2*)out + (size_t)gA * NN;
        float2* ogB = (float2*)out + (size_t)gB * NN;
        const char* pinc = (const char*)pb1;
        #pragma unroll 1
        for (int s = t; s < NN; s += bs) {
            int node = sperm[s];
            ull xA = __ldg(&xgA[node]);
            ull xB = __ldg(&xgB[node]);
            int b = sptr[s], e = sptr[s + 1];
            ulonglong2 m0 = pb0[s];
            ull a0 = m0.x, a1 = m0.y;
            #pragma unroll 1
            for (int q = b; q < e; q++) {
                int2 ed = sedge[q];
                float w = __int_as_float(ed.y);
                ull ww = pk2(w, w);
                ulonglong2 v = *(const ulonglong2*)(pinc + ed.x);
                a0 = fma2v(v.x, ww, a0);
                a1 = fma2v(v.y, ww, a1);
            }
            float ox, oy, xl, xh;
            upk2(a0, ox, oy); upk2(xA, xl, xh);
            ogA[node] = make_float2(xl + ox + b20, xh + oy + b21);
            if (hasB) {
                upk2(a1, ox, oy); upk2(xB, xl, xh);
                ogB[node] = make_float2(xl + ox + b20, xh + oy + b21);
            }
        }
    }
    #undef GATHER
}

// ---------------- launcher ----------------
extern "C" void kernel_launch(void* const* d_in, const int* in_sizes, int n_in,
                              void* d_out, int out_size) {
    const float* x   = (const float*)d_in[0];
    const int*   row = (const int*)  d_in[1];
    const int*   col = (const int*)  d_in[2];
    const float* ew  = (const float*)d_in[3];
    const float* W1  = (const float*)d_in[4];
    const float* b1  = (const float*)d_in[5];
    const float* W2  = (const float*)d_in[6];
    const float* b2  = (const float*)d_in[7];

    const int E = in_sizes[1];
    const int G = in_sizes[0] / (2 * NN);
    const int nCta = (G + 1) / 2;

    cudaFuncSetAttribute(k_main, cudaFuncAttributeMaxDynamicSharedMemorySize, SMEM_BYTES);

    k_main<<<nCta, TPB, SMEM_BYTES>>>(x, row, col, ew, W1, b1, W2, b2,
                                      (float*)d_out, G, E);
}